// round 2
// baseline (speedup 1.0000x reference)
#include <cuda_runtime.h>
#include <math.h>

// Problem dims (fixed by the dataset)
#define BROWS 1024      // 16*64
#define DDIM  8192
#define HDIM  1024
#define GGRP  8
#define SCDIM 2048      // S*C
#define XDIM  3072      // 3*H
#define KB1   4096      // 3H + D/G
#define NB2   3072      // 3*D/G
#define YDIM  24576     // 3*D

// Scratch (allocation-free rule: __device__ globals)
__device__ float g_x   [BROWS * XDIM];   // silu(rmsnorm(branches)) concat
__device__ float g_pre [BROWS * XDIM];   // branch pre-activations
__device__ float g_hpre[BROWS * DDIM];   // grouped gemm1 out + bias
__device__ float g_h   [BROWS * DDIM];   // silu(rmsnorm(h))
__device__ float g_y   [BROWS * YDIM];   // grouped gemm2 out + bias

// ---------------------------------------------------------------------------
// TN SGEMM: C[m,n] = sum_k A[m,k]*B[n,k] + bias[n]
// A: M x K (K-contig), B: N x K (K-contig). 64x64 tile, BK=16, 256 thr, 4x4.
// Grid: (N/64, M/64). Assumes M,N %64==0, K%16==0.
// ---------------------------------------------------------------------------
__global__ __launch_bounds__(256) void sgemm_tn64(
    const float* __restrict__ A, int lda,
    const float* __restrict__ Bm, int ldb,
    const float* __restrict__ bias,
    float* __restrict__ C, int ldc, int cOff,
    int K)
{
    __shared__ float As[16][68];
    __shared__ float Bs[16][68];

    const int t    = threadIdx.x;
    const int m0   = blockIdx.y * 64;
    const int n0   = blockIdx.x * 64;
    const int rowL = t >> 2;          // 0..63
    const int kc   = (t & 3) * 4;     // 0,4,8,12
    const int ty   = t >> 4;          // 0..15
    const int tx   = t & 15;          // 0..15

    float acc[4][4];
#pragma unroll
    for (int i = 0; i < 4; i++)
#pragma unroll
        for (int j = 0; j < 4; j++) acc[i][j] = 0.f;

    for (int k0 = 0; k0 < K; k0 += 16) {
        float4 av = *(const float4*)(A  + (size_t)(m0 + rowL) * lda + k0 + kc);
        float4 bv = *(const float4*)(Bm + (size_t)(n0 + rowL) * ldb + k0 + kc);
        As[kc + 0][rowL] = av.x; As[kc + 1][rowL] = av.y;
        As[kc + 2][rowL] = av.z; As[kc + 3][rowL] = av.w;
        Bs[kc + 0][rowL] = bv.x; Bs[kc + 1][rowL] = bv.y;
        Bs[kc + 2][rowL] = bv.z; Bs[kc + 3][rowL] = bv.w;
        __syncthreads();

#pragma unroll
        for (int k = 0; k < 16; k++) {
            float4 a4 = *(const float4*)&As[k][ty * 4];
            float4 b4 = *(const float4*)&Bs[k][tx * 4];
            float a[4] = {a4.x, a4.y, a4.z, a4.w};
            float b[4] = {b4.x, b4.y, b4.z, b4.w};
#pragma unroll
            for (int i = 0; i < 4; i++)
#pragma unroll
                for (int j = 0; j < 4; j++) acc[i][j] = fmaf(a[i], b[j], acc[i][j]);
        }
        __syncthreads();
    }

    float4 bi = *(const float4*)(bias + n0 + tx * 4);
#pragma unroll
    for (int i = 0; i < 4; i++) {
        float4 o;
        o.x = acc[i][0] + bi.x; o.y = acc[i][1] + bi.y;
        o.z = acc[i][2] + bi.z; o.w = acc[i][3] + bi.w;
        *(float4*)(C + (size_t)(m0 + ty * 4 + i) * ldc + cOff + n0 + tx * 4) = o;
    }
}

// ---------------------------------------------------------------------------
// Grouped NN SGEMM with concat-A:
// C[b, g, o] = sum_i Ain[b, g, i] * B[g, i, o] + bias[g*gsC + o]
// Ain[b,g,i] = (i < kSplit) ? A0[b*lda0 + g*gsA0 + i]
//                           : A1[b*lda1 + g*gsA1 + (i - kSplit)]
// 128x128 tile, BK=8, 256 thr, 8x8. Grid: (N/128, M/128, G).
// ---------------------------------------------------------------------------
__global__ __launch_bounds__(256) void sgemm_nn_grouped(
    const float* __restrict__ A0, int lda0, int gsA0,
    const float* __restrict__ A1, int lda1, int gsA1,
    int kSplit,
    const float* __restrict__ Bm, int ldb, long gsB,
    const float* __restrict__ bias,
    float* __restrict__ C, int ldc, int gsC,
    int K)
{
    __shared__ float As[8][132];
    __shared__ float Bs[8][128];

    const int t  = threadIdx.x;
    const int g  = blockIdx.z;
    const int m0 = blockIdx.y * 128;
    const int n0 = blockIdx.x * 128;
    const int rA = t >> 1;           // 0..127
    const int ka = (t & 1) * 4;      // 0 or 4
    const int kb = t >> 5;           // 0..7
    const int nb = (t & 31) * 4;     // 0..124
    const int ty = t >> 4;           // 0..15
    const int tx = t & 15;           // 0..15

    const float* Bg = Bm + (size_t)g * gsB;

    float acc[8][8];
#pragma unroll
    for (int i = 0; i < 8; i++)
#pragma unroll
        for (int j = 0; j < 8; j++) acc[i][j] = 0.f;

    for (int k0 = 0; k0 < K; k0 += 8) {
        const int i = k0 + ka;
        const float* ap = (i < kSplit)
            ? A0 + (size_t)(m0 + rA) * lda0 + (size_t)g * gsA0 + i
            : A1 + (size_t)(m0 + rA) * lda1 + (size_t)g * gsA1 + (i - kSplit);
        float4 av = *(const float4*)ap;
        As[ka + 0][rA] = av.x; As[ka + 1][rA] = av.y;
        As[ka + 2][rA] = av.z; As[ka + 3][rA] = av.w;

        float4 bv = *(const float4*)(Bg + (size_t)(k0 + kb) * ldb + n0 + nb);
        *(float4*)&Bs[kb][nb] = bv;
        __syncthreads();

#pragma unroll
        for (int k = 0; k < 8; k++) {
            float a[8], b[8];
            *(float4*)&a[0] = *(const float4*)&As[k][ty * 8];
            *(float4*)&a[4] = *(const float4*)&As[k][ty * 8 + 4];
            *(float4*)&b[0] = *(const float4*)&Bs[k][tx * 8];
            *(float4*)&b[4] = *(const float4*)&Bs[k][tx * 8 + 4];
#pragma unroll
            for (int ii = 0; ii < 8; ii++)
#pragma unroll
                for (int jj = 0; jj < 8; jj++) acc[ii][jj] = fmaf(a[ii], b[jj], acc[ii][jj]);
        }
        __syncthreads();
    }

    const float* biasg = bias + (size_t)g * gsC + n0 + tx * 8;
    float4 bi0 = *(const float4*)(biasg);
    float4 bi1 = *(const float4*)(biasg + 4);
#pragma unroll
    for (int i = 0; i < 8; i++) {
        float* crow = C + (size_t)(m0 + ty * 8 + i) * ldc + (size_t)g * gsC + n0 + tx * 8;
        float4 o0, o1;
        o0.x = acc[i][0] + bi0.x; o0.y = acc[i][1] + bi0.y;
        o0.z = acc[i][2] + bi0.z; o0.w = acc[i][3] + bi0.w;
        o1.x = acc[i][4] + bi1.x; o1.y = acc[i][5] + bi1.y;
        o1.z = acc[i][6] + bi1.z; o1.w = acc[i][7] + bi1.w;
        *(float4*)(crow)     = o0;
        *(float4*)(crow + 4) = o1;
    }
}

// ---------------------------------------------------------------------------
// Branch 3: normalize action, tiny matvec (A=2) + bias
// ---------------------------------------------------------------------------
__global__ __launch_bounds__(256) void branch3_kernel(
    const float* __restrict__ action,
    const float* __restrict__ W3,
    const float* __restrict__ b3)
{
    const int b = blockIdx.x;
    float a0 = action[b * 2 + 0];
    float a1 = action[b * 2 + 1];
    a0 = a0 / fmaxf(1.f, fabsf(a0));
    a1 = a1 / fmaxf(1.f, fabsf(a1));
    for (int h = threadIdx.x; h < HDIM; h += blockDim.x) {
        g_pre[(size_t)b * XDIM + 2048 + h] =
            fmaf(a0, W3[h * 2 + 0], fmaf(a1, W3[h * 2 + 1], b3[h]));
    }
}

// ---------------------------------------------------------------------------
// rmsnorm(x, scale) followed by SiLU. One block per row. L % 4 == 0.
// ---------------------------------------------------------------------------
__global__ __launch_bounds__(256) void rmsnorm_silu_kernel(
    const float* __restrict__ src, int ldsrc, int osrc,
    float* __restrict__ dst, int lddst, int odst,
    const float* __restrict__ scale, int L)
{
    const int b   = blockIdx.x;
    const int tid = threadIdx.x;
    const float4* r4 = (const float4*)(src + (size_t)b * ldsrc + osrc);
    const float4* s4 = (const float4*)scale;
    float4*       d4 = (float4*)(dst + (size_t)b * lddst + odst);
    const int nv = L / 4;

    float ss = 0.f;
    for (int j = tid; j < nv; j += 256) {
        float4 v = r4[j];
        ss += v.x * v.x + v.y * v.y + v.z * v.z + v.w * v.w;
    }
    __shared__ float red[256];
    red[tid] = ss;
    __syncthreads();
#pragma unroll
    for (int s = 128; s > 0; s >>= 1) {
        if (tid < s) red[tid] += red[tid + s];
        __syncthreads();
    }
    const float rms = rsqrtf(red[0] / (float)L + 1e-6f);

    for (int j = tid; j < nv; j += 256) {
        float4 v = r4[j];
        float4 sc = s4[j];
        float t0 = v.x * rms * sc.x;
        float t1 = v.y * rms * sc.y;
        float t2 = v.z * rms * sc.z;
        float t3 = v.w * rms * sc.w;
        float4 o;
        o.x = t0 / (1.f + expf(-t0));
        o.y = t1 / (1.f + expf(-t1));
        o.z = t2 / (1.f + expf(-t2));
        o.w = t3 / (1.f + expf(-t3));
        d4[j] = o;
    }
}

// ---------------------------------------------------------------------------
// Final GRU-style gate math
// ---------------------------------------------------------------------------
__global__ __launch_bounds__(256) void gate_kernel(
    const float* __restrict__ deter, float* __restrict__ out)
{
    const int idx = blockIdx.x * blockDim.x + threadIdx.x;  // < 1024*8192
    const int b  = idx >> 13;
    const int gd = idx & 8191;
    const int g  = gd >> 10;
    const int m  = gd & 1023;
    const float* yb = g_y + (size_t)b * YDIM + g * NB2;
    const float r = yb[m];
    const float c = yb[1024 + m];
    const float u = yb[2048 + m];
    const float reset  = 1.f / (1.f + expf(-r));
    const float cand   = tanhf(reset * c);
    const float update = 1.f / (1.f + expf(-(u - 1.f)));
    out[idx] = update * cand + (1.f - update) * deter[idx];
}

// ---------------------------------------------------------------------------
extern "C" void kernel_launch(void* const* d_in, const int* in_sizes, int n_in,
                              void* d_out, int out_size)
{
    const float* deter  = (const float*)d_in[0];
    const float* stoch  = (const float*)d_in[1];
    const float* action = (const float*)d_in[2];
    const float* W1  = (const float*)d_in[3];
    const float* b1  = (const float*)d_in[4];
    const float* s1  = (const float*)d_in[5];
    const float* W2  = (const float*)d_in[6];
    const float* b2  = (const float*)d_in[7];
    const float* s2  = (const float*)d_in[8];
    const float* W3  = (const float*)d_in[9];
    const float* b3  = (const float*)d_in[10];
    const float* s3  = (const float*)d_in[11];
    const float* Wb1 = (const float*)d_in[12];
    const float* bb1 = (const float*)d_in[13];
    const float* sb1 = (const float*)d_in[14];
    const float* Wb2 = (const float*)d_in[15];
    const float* bb2 = (const float*)d_in[16];
    float* out = (float*)d_out;

    float *xp, *prep, *hprep, *hp;
    cudaGetSymbolAddress((void**)&xp,    g_x);
    cudaGetSymbolAddress((void**)&prep,  g_pre);
    cudaGetSymbolAddress((void**)&hprep, g_hpre);
    cudaGetSymbolAddress((void**)&hp,    g_h);
    float* yp;
    cudaGetSymbolAddress((void**)&yp,    g_y);

    // Branch pre-activations (disjoint column blocks of g_pre)
    sgemm_tn64<<<dim3(16, 16), 256>>>(deter, DDIM,  W1, DDIM,  b1, prep, XDIM, 0,    DDIM);
    sgemm_tn64<<<dim3(16, 16), 256>>>(stoch, SCDIM, W2, SCDIM, b2, prep, XDIM, 1024, SCDIM);
    branch3_kernel<<<BROWS, 256>>>(action, W3, b3);

    // Per-branch rmsnorm + SiLU -> g_x
    rmsnorm_silu_kernel<<<BROWS, 256>>>(prep, XDIM, 0,    xp, XDIM, 0,    s1, HDIM);
    rmsnorm_silu_kernel<<<BROWS, 256>>>(prep, XDIM, 1024, xp, XDIM, 1024, s2, HDIM);
    rmsnorm_silu_kernel<<<BROWS, 256>>>(prep, XDIM, 2048, xp, XDIM, 2048, s3, HDIM);

    // Grouped GEMM 1: [x | d_g] @ Wb1[g] + bb1 -> g_hpre (B x 8192)
    sgemm_nn_grouped<<<dim3(8, 8, GGRP), 256>>>(
        xp, XDIM, 0,          // A0 = x, shared across groups
        deter, DDIM, 1024,    // A1 = d group slice
        3072,                 // kSplit
        Wb1, 1024, (long)KB1 * 1024,
        bb1,
        hprep, DDIM, 1024,
        KB1);

    // rmsnorm + SiLU over full row (L=8192) -> g_h
    rmsnorm_silu_kernel<<<BROWS, 256>>>(hprep, DDIM, 0, hp, DDIM, 0, sb1, DDIM);

    // Grouped GEMM 2: h_g @ Wb2[g] + bb2 -> g_y (B x 24576)
    sgemm_nn_grouped<<<dim3(24, 8, GGRP), 256>>>(
        hp, DDIM, 1024,
        hp, DDIM, 1024,       // unused (kSplit == K)
        1024,
        Wb2, NB2, (long)1024 * NB2,
        bb2,
        yp, YDIM, NB2,
        1024);

    // Gates -> out
    gate_kernel<<<(BROWS * DDIM) / 256, 256>>>(deter, out);
}

// round 4
// speedup vs baseline: 4.3341x; 4.3341x over previous
#include <cuda_runtime.h>
#include <cuda_bf16.h>
#include <cstdint>
#include <math.h>

#define BROWS 1024
#define DDIM  8192
#define HDIM  1024
#define GGRP  8
#define SCDIM 2048
#define XDIM  3072
#define KB1   4096
#define NB2   3072
#define YDIM  24576

// ---------------- scratch (__device__ globals; no allocs allowed) ----------
__device__ float g_pre [BROWS * XDIM];
__device__ float g_hpre[BROWS * DDIM];
__device__ float g_y   [BROWS * YDIM];

__device__ __nv_bfloat16 g_d16 [BROWS * DDIM];
__device__ __nv_bfloat16 g_s16 [BROWS * SCDIM];
__device__ __nv_bfloat16 g_w1  [HDIM * DDIM];
__device__ __nv_bfloat16 g_w2  [HDIM * SCDIM];
__device__ __nv_bfloat16 g_wb1t[(size_t)GGRP * HDIM * KB1];   // [g][o=1024][i=4096]
__device__ __nv_bfloat16 g_wb2t[(size_t)GGRP * NB2 * HDIM];   // [g][o=3072][i=1024]
__device__ __nv_bfloat16 g_x16 [BROWS * XDIM];
__device__ __nv_bfloat16 g_h16 [BROWS * DDIM];

// ---------------- helpers --------------------------------------------------
__device__ __forceinline__ uint32_t smem_u32(const void* p) {
    uint32_t a;
    asm("{ .reg .u64 t; cvta.to.shared.u64 t, %1; cvt.u32.u64 %0, t; }" : "=r"(a) : "l"(p));
    return a;
}
#define CP16(s, gp) \
    asm volatile("cp.async.cg.shared.global [%0], [%1], 16;" :: "r"(s), "l"(gp))
#define CP_COMMIT() asm volatile("cp.async.commit_group;" ::: "memory")

__device__ __forceinline__ void ldmx4(uint32_t& r0, uint32_t& r1, uint32_t& r2, uint32_t& r3,
                                      uint32_t addr) {
    asm volatile("ldmatrix.sync.aligned.m8n8.x4.shared.b16 {%0,%1,%2,%3}, [%4];"
                 : "=r"(r0), "=r"(r1), "=r"(r2), "=r"(r3) : "r"(addr));
}
__device__ __forceinline__ void mma16816(float* c, const uint32_t* a, const uint32_t* b) {
    asm volatile("mma.sync.aligned.m16n8k16.row.col.f32.bf16.bf16.f32 "
                 "{%0,%1,%2,%3}, {%4,%5,%6,%7}, {%8,%9}, {%0,%1,%2,%3};"
                 : "+f"(c[0]), "+f"(c[1]), "+f"(c[2]), "+f"(c[3])
                 : "r"(a[0]), "r"(a[1]), "r"(a[2]), "r"(a[3]), "r"(b[0]), "r"(b[1]));
}

// ---------------- HMMA GEMM ------------------------------------------------
// C[b, g*gsC + n] = sum_k Ain[b,g,k] * B[g,n,k] + bias[g*gsBias + n]
// Ain = (k < kSplit) ? A0[b*ldA0 + g*gsA0 + k] : A1[b*ldA1 + g*gsA1 + (k-kSplit)]
// Tile: 128(M) x 128(N) x 32(K). 256 threads, 8 warps (4 in M x 2 in N), warp 32x64.
// SMEM rows padded to 40 bf16 (80B): ldmatrix conflict-free.
#define BKE   32
#define LDS_P 40
#define ASTG  (128 * LDS_P * 2)       // 10240 B per stage

__global__ __launch_bounds__(256) void gemm_mma(
    const __nv_bfloat16* __restrict__ A0, long ldA0, long gsA0,
    const __nv_bfloat16* __restrict__ A1, long ldA1, long gsA1, int kSplit,
    const __nv_bfloat16* __restrict__ B,  long ldB,  long gsB,
    const float* __restrict__ bias, long gsBias,
    float* __restrict__ C, long ldc, long gsC,
    int K)
{
    __shared__ __align__(16) char smem[4 * ASTG];  // A0,A1 | B0,B1
    const uint32_t sb = smem_u32(smem);
    const int t    = threadIdx.x;
    const int lane = t & 31;
    const int wid  = t >> 5;
    const int wm   = wid & 3;          // 0..3 -> M offset wm*32
    const int wn   = wid >> 2;         // 0..1 -> N offset wn*64
    const int g  = blockIdx.z;
    const int m0 = blockIdx.y * 128;
    const int n0 = blockIdx.x * 128;

    const int lrow = t >> 1;           // 0..127
    const int lhalf = (t & 1) * 16;    // 0 or 16 (elements)

    float acc[2][8][4];
#pragma unroll
    for (int i = 0; i < 2; i++)
#pragma unroll
        for (int j = 0; j < 8; j++)
#pragma unroll
            for (int r = 0; r < 4; r++) acc[i][j][r] = 0.f;

    const int nkb = K / BKE;

    // ---- stage loader ----
    auto load_stage = [&](int buf, int kb) {
        const int k0 = kb * BKE;
        const __nv_bfloat16* ag;
        if (k0 < kSplit)
            ag = A0 + (size_t)(m0 + lrow) * ldA0 + (size_t)g * gsA0 + k0 + lhalf;
        else
            ag = A1 + (size_t)(m0 + lrow) * ldA1 + (size_t)g * gsA1 + (k0 - kSplit) + lhalf;
        uint32_t ad = sb + buf * ASTG + (uint32_t)(lrow * LDS_P + lhalf) * 2;
        CP16(ad, ag);
        CP16(ad + 16, ag + 8);

        const __nv_bfloat16* bg =
            B + (size_t)g * gsB + (size_t)(n0 + lrow) * ldB + k0 + lhalf;
        uint32_t bd = sb + 2 * ASTG + buf * ASTG + (uint32_t)(lrow * LDS_P + lhalf) * 2;
        CP16(bd, bg);
        CP16(bd + 16, bg + 8);
        CP_COMMIT();
    };

    load_stage(0, 0);

    for (int kb = 0; kb < nkb; kb++) {
        const int buf = kb & 1;
        if (kb + 1 < nkb) {
            load_stage(buf ^ 1, kb + 1);
            asm volatile("cp.async.wait_group 1;" ::: "memory");
        } else {
            asm volatile("cp.async.wait_group 0;" ::: "memory");
        }
        __syncthreads();

        const uint32_t aS = sb + buf * ASTG;
        const uint32_t bS = sb + 2 * ASTG + buf * ASTG;
#pragma unroll
        for (int ks = 0; ks < 2; ks++) {
            uint32_t a[2][4];
#pragma unroll
            for (int mi = 0; mi < 2; mi++) {
                uint32_t ra = aS + (uint32_t)((wm * 32 + mi * 16 + (lane & 15)) * LDS_P
                                              + ks * 16 + (lane >> 4) * 8) * 2;
                ldmx4(a[mi][0], a[mi][1], a[mi][2], a[mi][3], ra);
            }
            uint32_t b[8][2];
#pragma unroll
            for (int np = 0; np < 4; np++) {
                uint32_t rb = bS + (uint32_t)((wn * 64 + np * 16 + ((lane >> 4) << 3) + (lane & 7)) * LDS_P
                                              + ks * 16 + ((lane >> 3) & 1) * 8) * 2;
                ldmx4(b[2 * np][0], b[2 * np][1], b[2 * np + 1][0], b[2 * np + 1][1], rb);
            }
#pragma unroll
            for (int mi = 0; mi < 2; mi++)
#pragma unroll
                for (int ni = 0; ni < 8; ni++)
                    mma16816(acc[mi][ni], a[mi], b[ni]);
        }
        __syncthreads();
    }

    // ---- epilogue: bias add + fp32 store ----
    const float* bg = bias + (size_t)g * gsBias + n0 + wn * 64;
#pragma unroll
    for (int mi = 0; mi < 2; mi++) {
        const int r0 = m0 + wm * 32 + mi * 16 + (lane >> 2);
        float* c0 = C + (size_t)r0 * ldc + (size_t)g * gsC + n0 + wn * 64;
        float* c1 = c0 + 8 * ldc;
#pragma unroll
        for (int ni = 0; ni < 8; ni++) {
            const int col = ni * 8 + (lane & 3) * 2;
            const float bx = bg[col], by = bg[col + 1];
            float2 v0 = make_float2(acc[mi][ni][0] + bx, acc[mi][ni][1] + by);
            float2 v1 = make_float2(acc[mi][ni][2] + bx, acc[mi][ni][3] + by);
            *(float2*)(c0 + col) = v0;
            *(float2*)(c1 + col) = v1;
        }
    }
}

// ---------------- conversion / transpose ----------------------------------
__global__ __launch_bounds__(256) void f32_to_bf16_kernel(
    const float* __restrict__ in, __nv_bfloat16* __restrict__ out, int n4)
{
    int i = blockIdx.x * blockDim.x + threadIdx.x;
    if (i >= n4) return;
    float4 v = ((const float4*)in)[i];
    ushort4 u;
    u.x = __bfloat16_as_ushort(__float2bfloat16(v.x));
    u.y = __bfloat16_as_ushort(__float2bfloat16(v.y));
    u.z = __bfloat16_as_ushort(__float2bfloat16(v.z));
    u.w = __bfloat16_as_ushort(__float2bfloat16(v.w));
    ((ushort4*)out)[i] = u;
}

// in[g][r][c] (fp32) -> out[g][c][r] (bf16). grid (C/32, R/32, G), block (32, 8)
__global__ __launch_bounds__(256) void transpose_to_bf16(
    const float* __restrict__ in, __nv_bfloat16* __restrict__ out, int R, int Cc)
{
    __shared__ float tile[32][33];
    const int g = blockIdx.z;
    const float* ing = in + (size_t)g * R * Cc;
    __nv_bfloat16* og = out + (size_t)g * R * Cc;
    const int c0 = blockIdx.x * 32, r0 = blockIdx.y * 32;
    const int tx = threadIdx.x, ty = threadIdx.y;
#pragma unroll
    for (int k = 0; k < 32; k += 8)
        tile[ty + k][tx] = ing[(size_t)(r0 + ty + k) * Cc + c0 + tx];
    __syncthreads();
#pragma unroll
    for (int k = 0; k < 32; k += 8)
        og[(size_t)(c0 + ty + k) * R + r0 + tx] = __float2bfloat16(tile[tx][ty + k]);
}

// ---------------- small fused kernels --------------------------------------
__global__ __launch_bounds__(256) void branch3_kernel(
    const float* __restrict__ action,
    const float* __restrict__ W3,
    const float* __restrict__ b3)
{
    const int b = blockIdx.x;
    float a0 = action[b * 2 + 0];
    float a1 = action[b * 2 + 1];
    a0 = a0 / fmaxf(1.f, fabsf(a0));
    a1 = a1 / fmaxf(1.f, fabsf(a1));
    for (int h = threadIdx.x; h < HDIM; h += blockDim.x) {
        g_pre[(size_t)b * XDIM + 2048 + h] =
            fmaf(a0, W3[h * 2 + 0], fmaf(a1, W3[h * 2 + 1], b3[h]));
    }
}

__global__ __launch_bounds__(256) void rmsnorm_silu_bf16(
    const float* __restrict__ src, int ldsrc, int osrc,
    __nv_bfloat16* __restrict__ dst, int lddst, int odst,
    const float* __restrict__ scale, int L)
{
    const int b   = blockIdx.x;
    const int tid = threadIdx.x;
    const float4* r4 = (const float4*)(src + (size_t)b * ldsrc + osrc);
    const float4* s4 = (const float4*)scale;
    ushort4* d4 = (ushort4*)(dst + (size_t)b * lddst + odst);
    const int nv = L / 4;

    float ss = 0.f;
    for (int j = tid; j < nv; j += 256) {
        float4 v = r4[j];
        ss += v.x * v.x + v.y * v.y + v.z * v.z + v.w * v.w;
    }
    __shared__ float red[256];
    red[tid] = ss;
    __syncthreads();
#pragma unroll
    for (int s = 128; s > 0; s >>= 1) {
        if (tid < s) red[tid] += red[tid + s];
        __syncthreads();
    }
    const float rms = rsqrtf(red[0] / (float)L + 1e-6f);

    for (int j = tid; j < nv; j += 256) {
        float4 v = r4[j];
        float4 sc = s4[j];
        float t0 = v.x * rms * sc.x;
        float t1 = v.y * rms * sc.y;
        float t2 = v.z * rms * sc.z;
        float t3 = v.w * rms * sc.w;
        ushort4 o;
        o.x = __bfloat16_as_ushort(__float2bfloat16(t0 / (1.f + expf(-t0))));
        o.y = __bfloat16_as_ushort(__float2bfloat16(t1 / (1.f + expf(-t1))));
        o.z = __bfloat16_as_ushort(__float2bfloat16(t2 / (1.f + expf(-t2))));
        o.w = __bfloat16_as_ushort(__float2bfloat16(t3 / (1.f + expf(-t3))));
        d4[j] = o;
    }
}

__global__ __launch_bounds__(256) void gate_kernel(
    const float* __restrict__ deter, float* __restrict__ out)
{
    const int idx = blockIdx.x * blockDim.x + threadIdx.x;
    const int b  = idx >> 13;
    const int gd = idx & 8191;
    const int g  = gd >> 10;
    const int m  = gd & 1023;
    const float* yb = g_y + (size_t)b * YDIM + g * NB2;
    const float r = yb[m];
    const float c = yb[1024 + m];
    const float u = yb[2048 + m];
    const float reset  = 1.f / (1.f + expf(-r));
    const float cand   = tanhf(reset * c);
    const float update = 1.f / (1.f + expf(-(u - 1.f)));
    out[idx] = update * cand + (1.f - update) * deter[idx];
}

// ---------------------------------------------------------------------------
extern "C" void kernel_launch(void* const* d_in, const int* in_sizes, int n_in,
                              void* d_out, int out_size)
{
    const float* deter  = (const float*)d_in[0];
    const float* stoch  = (const float*)d_in[1];
    const float* action = (const float*)d_in[2];
    const float* W1  = (const float*)d_in[3];
    const float* b1  = (const float*)d_in[4];
    const float* s1  = (const float*)d_in[5];
    const float* W2  = (const float*)d_in[6];
    const float* b2  = (const float*)d_in[7];
    const float* s2  = (const float*)d_in[8];
    const float* W3  = (const float*)d_in[9];
    const float* b3  = (const float*)d_in[10];
    const float* s3  = (const float*)d_in[11];
    const float* Wb1 = (const float*)d_in[12];
    const float* bb1 = (const float*)d_in[13];
    const float* sb1 = (const float*)d_in[14];
    const float* Wb2 = (const float*)d_in[15];
    const float* bb2 = (const float*)d_in[16];
    float* out = (float*)d_out;

    float *prep, *hprep, *yp;
    __nv_bfloat16 *d16, *s16, *w1p, *w2p, *wb1t, *wb2t, *x16, *h16;
    cudaGetSymbolAddress((void**)&prep,  g_pre);
    cudaGetSymbolAddress((void**)&hprep, g_hpre);
    cudaGetSymbolAddress((void**)&yp,    g_y);
    cudaGetSymbolAddress((void**)&d16,   g_d16);
    cudaGetSymbolAddress((void**)&s16,   g_s16);
    cudaGetSymbolAddress((void**)&w1p,   g_w1);
    cudaGetSymbolAddress((void**)&w2p,   g_w2);
    cudaGetSymbolAddress((void**)&wb1t,  g_wb1t);
    cudaGetSymbolAddress((void**)&wb2t,  g_wb2t);
    cudaGetSymbolAddress((void**)&x16,   g_x16);
    cudaGetSymbolAddress((void**)&h16,   g_h16);

    // fp32 -> bf16 conversions (K-major layouts preserved)
    f32_to_bf16_kernel<<<(BROWS * DDIM / 4 + 255) / 256, 256>>>(deter, d16, BROWS * DDIM / 4);
    f32_to_bf16_kernel<<<(BROWS * SCDIM / 4 + 255) / 256, 256>>>(stoch, s16, BROWS * SCDIM / 4);
    f32_to_bf16_kernel<<<(HDIM * DDIM / 4 + 255) / 256, 256>>>(W1, w1p, HDIM * DDIM / 4);
    f32_to_bf16_kernel<<<(HDIM * SCDIM / 4 + 255) / 256, 256>>>(W2, w2p, HDIM * SCDIM / 4);
    // Wb1[g][i=4096][o=1024] -> [g][o][i] ; Wb2[g][i=1024][o=3072] -> [g][o][i]
    transpose_to_bf16<<<dim3(1024 / 32, 4096 / 32, GGRP), dim3(32, 8)>>>(Wb1, wb1t, 4096, 1024);
    transpose_to_bf16<<<dim3(3072 / 32, 1024 / 32, GGRP), dim3(32, 8)>>>(Wb2, wb2t, 1024, 3072);

    // Branch GEMMs -> g_pre (fp32 preacts). kSplit=K so A1 path unused.
    gemm_mma<<<dim3(8, 8, 1), 256>>>(
        d16, DDIM, 0,  d16, DDIM, 0, DDIM,
        w1p, DDIM, 0,  b1, 0,
        prep, XDIM, 0, DDIM);
    gemm_mma<<<dim3(8, 8, 1), 256>>>(
        s16, SCDIM, 0, s16, SCDIM, 0, SCDIM,
        w2p, SCDIM, 0, b2, 0,
        prep + 1024, XDIM, 0, SCDIM);
    branch3_kernel<<<BROWS, 256>>>(action, W3, b3);

    // rmsnorm + SiLU -> bf16 x
    rmsnorm_silu_bf16<<<BROWS, 256>>>(prep, XDIM, 0,    x16, XDIM, 0,    s1, HDIM);
    rmsnorm_silu_bf16<<<BROWS, 256>>>(prep, XDIM, 1024, x16, XDIM, 1024, s2, HDIM);
    rmsnorm_silu_bf16<<<BROWS, 256>>>(prep, XDIM, 2048, x16, XDIM, 2048, s3, HDIM);

    // Grouped GEMM 1: [x | d_g] @ Wb1t[g] -> g_hpre (B x 8192)
    gemm_mma<<<dim3(8, 8, GGRP), 256>>>(
        x16, XDIM, 0,
        d16, DDIM, 1024, XDIM,
        wb1t, KB1, (long)HDIM * KB1,
        bb1, HDIM,
        hprep, DDIM, HDIM, KB1);

    rmsnorm_silu_bf16<<<BROWS, 256>>>(hprep, DDIM, 0, h16, DDIM, 0, sb1, DDIM);

    // Grouped GEMM 2: h_g @ Wb2t[g] -> g_y (B x 24576)
    gemm_mma<<<dim3(24, 8, GGRP), 256>>>(
        h16, DDIM, 1024,
        h16, DDIM, 1024, HDIM,
        wb2t, HDIM, (long)NB2 * HDIM,
        bb2, NB2,
        yp, YDIM, NB2, HDIM);

    gate_kernel<<<(BROWS * DDIM) / 256, 256>>>(deter, out);
}